// round 13
// baseline (speedup 1.0000x reference)
#include <cuda_runtime.h>
#include <cuda_bf16.h>
#include <mma.h>
#include <cstdint>

using namespace nvcuda;

#define BN   4
#define LL   512
#define HH   768
#define HSZ  64
#define NOUT 16
#define NTOK (BN*LL)      // 2048
#define NP   131328       // L*(L+1)/2

// scratch (allocation-free rule: __device__ globals)
__device__ __align__(16) __nv_bfloat16 g_xhi[NTOK*HH];   // 3 MB
__device__ __align__(16) __nv_bfloat16 g_xlo[NTOK*HH];   // 3 MB
__device__ __align__(16) __nv_bfloat16 g_whi[HH*128];    // 192 KB  [k][n] n<64:Wq else Wk
__device__ __align__(16) __nv_bfloat16 g_wlo[HH*128];    // 192 KB
__device__ float g_q[NTOK*HSZ];        // 512 KB
__device__ float g_k[NTOK*HSZ];        // 512 KB
__device__ float g_A[NTOK*NOUT];       // 128 KB
__device__ float g_E[NTOK*NOUT];       // 128 KB

// ---------------------------------------------------------------------------
// Kernel 1: prep — bf16 hi/lo images of X (row-major [tok][k]) and W
// (row-major [k][n], n<64 = Wq col, else Wk col). Blocks [0,1536): X,
// [1536,1632): W.
// ---------------------------------------------------------------------------
__global__ __launch_bounds__(256) void prep_kernel(
    const float* __restrict__ x,
    const float* __restrict__ Wq,
    const float* __restrict__ Wk)
{
    const int gid = blockIdx.x * 256 + threadIdx.x;
    if (blockIdx.x < 1536) {
        // X: 2048 tok x 192 float4 quads
        size_t idx = (size_t)gid * 4;
        float4 v = *(const float4*)&x[idx];
        float f[4] = {v.x, v.y, v.z, v.w};
        unsigned short h[4], l[4];
        #pragma unroll
        for (int i = 0; i < 4; i++) {
            __nv_bfloat16 hb = __float2bfloat16(f[i]);
            __nv_bfloat16 lb = __float2bfloat16(f[i] - __bfloat162float(hb));
            h[i] = __bfloat16_as_ushort(hb);
            l[i] = __bfloat16_as_ushort(lb);
        }
        *(uint2*)&g_xhi[idx] = make_uint2((uint32_t)h[0] | ((uint32_t)h[1] << 16),
                                          (uint32_t)h[2] | ((uint32_t)h[3] << 16));
        *(uint2*)&g_xlo[idx] = make_uint2((uint32_t)l[0] | ((uint32_t)l[1] << 16),
                                          (uint32_t)l[2] | ((uint32_t)l[3] << 16));
    } else {
        // W: 768 k x 32 quads (128 n)
        int id = gid - 1536 * 256;            // 0..24575
        int k  = id >> 5;
        int n  = (id & 31) * 4;
        unsigned short h[4], l[4];
        #pragma unroll
        for (int i = 0; i < 4; i++) {
            int nn = n + i;
            float s = (nn < 64) ? Wq[(size_t)k * HSZ + nn]
                                : Wk[(size_t)k * HSZ + (nn - 64)];
            __nv_bfloat16 hb = __float2bfloat16(s);
            __nv_bfloat16 lb = __float2bfloat16(s - __bfloat162float(hb));
            h[i] = __bfloat16_as_ushort(hb);
            l[i] = __bfloat16_as_ushort(lb);
        }
        size_t o = (size_t)k * 128 + n;
        *(uint2*)&g_whi[o] = make_uint2((uint32_t)h[0] | ((uint32_t)h[1] << 16),
                                        (uint32_t)h[2] | ((uint32_t)h[3] << 16));
        *(uint2*)&g_wlo[o] = make_uint2((uint32_t)l[0] | ((uint32_t)l[1] << 16),
                                        (uint32_t)l[2] | ((uint32_t)l[3] << 16));
    }
}

// ---------------------------------------------------------------------------
// Kernel 2: WMMA bf16 split GEMM (HMMA — no sm_103a features needed).
// Grid = 64 token-tiles x 2 col-halves = 128 blocks. Block tile 32 tok x
// 64 cols; 8 warps in 2(m) x 4(n); warp tile 16x16 = 1 acc fragment.
// K = 768 in 12 chunks of 64; per k16 step: 4 frag loads + 3 mma_sync
// (hi*hi, hi*lo, lo*hi). Epilogue: +bias -> g_q / g_k.
// ---------------------------------------------------------------------------
__global__ __launch_bounds__(256) void wmma_proj_kernel(
    const float* __restrict__ bq, const float* __restrict__ bk)
{
    __shared__ __nv_bfloat16 Ah[32][80], Al[32][80];   // ld=80 (160B, LDSM-friendly)
    __shared__ __nv_bfloat16 Bh[64][80], Bl[64][80];
    __shared__ float Cs[32][80];
    __shared__ float bias[64];

    const int tid  = threadIdx.x;
    const int warp = tid >> 5;
    const int tt   = blockIdx.x >> 1;     // 64 token tiles of 32
    const int cc   = blockIdx.x & 1;      // 0 -> q cols, 1 -> k cols
    const int t0   = tt * 32;

    if (tid < 64) bias[tid] = cc ? bk[tid] : bq[tid];

    const int m0 = (warp & 1) * 16;
    const int n0 = (warp >> 1) * 16;

    wmma::fragment<wmma::accumulator, 16, 16, 16, float> acc;
    wmma::fill_fragment(acc, 0.f);

    for (int c = 0; c < 12; c++) {
        const int k0 = c * 64;
        __syncthreads();   // previous iter's frag reads done before overwrite
        // stage A hi/lo: 32 rows x 16 quads each
        #pragma unroll
        for (int p = 0; p < 2; p++) {
            int e = tid + p * 256;         // 0..511
            int r = e >> 4, q = (e & 15) * 4;
            size_t go = (size_t)(t0 + r) * HH + k0 + q;
            *(uint2*)&Ah[r][q] = *(const uint2*)&g_xhi[go];
            *(uint2*)&Al[r][q] = *(const uint2*)&g_xlo[go];
        }
        // stage B hi/lo: 64 rows x 16 quads each (cols cc*64 .. +63)
        #pragma unroll
        for (int p = 0; p < 4; p++) {
            int e = tid + p * 256;         // 0..1023
            int r = e >> 4, q = (e & 15) * 4;
            size_t go = (size_t)(k0 + r) * 128 + cc * 64 + q;
            *(uint2*)&Bh[r][q] = *(const uint2*)&g_whi[go];
            *(uint2*)&Bl[r][q] = *(const uint2*)&g_wlo[go];
        }
        __syncthreads();

        #pragma unroll
        for (int ks = 0; ks < 4; ks++) {
            wmma::fragment<wmma::matrix_a, 16, 16, 16, __nv_bfloat16, wmma::row_major> ah, al;
            wmma::fragment<wmma::matrix_b, 16, 16, 16, __nv_bfloat16, wmma::row_major> bh, bl;
            wmma::load_matrix_sync(ah, &Ah[m0][ks * 16], 80);
            wmma::load_matrix_sync(al, &Al[m0][ks * 16], 80);
            wmma::load_matrix_sync(bh, &Bh[ks * 16][n0], 80);
            wmma::load_matrix_sync(bl, &Bl[ks * 16][n0], 80);
            wmma::mma_sync(acc, ah, bh, acc);
            wmma::mma_sync(acc, ah, bl, acc);
            wmma::mma_sync(acc, al, bh, acc);
        }
    }

    __syncthreads();
    wmma::store_matrix_sync(&Cs[m0][n0], acc, 80, wmma::mem_row_major);
    __syncthreads();

    float* dst = (cc ? g_k : g_q) + (size_t)t0 * HSZ;
    #pragma unroll
    for (int p = 0; p < 8; p++) {
        int e = tid + p * 256;             // 0..2047
        int r = e >> 6, col = e & 63;
        dst[r * HSZ + col] = Cs[r][col] + bias[col];
    }
}

// ---------------------------------------------------------------------------
// Kernel 3: A/E tables from g_q/g_k.
// A[s,o] = q[s]@Wb[0:64] + bb
// E[e,o] = k[e]@(Wb[64:128]+Wb[192:256]) + q[e]@Wb[128:192]
// ---------------------------------------------------------------------------
__global__ __launch_bounds__(256) void reduce_ae_kernel(
    const float* __restrict__ bb, const float* __restrict__ Wb)
{
    __shared__ float Wbs[256 * NOUT];
    __shared__ float sQK[32][132];
    __shared__ float bbs[NOUT];

    const int tid = threadIdx.x;
    const int t0  = blockIdx.x * 32;

    #pragma unroll
    for (int p = 0; p < 16; p++)
        Wbs[tid + p * 256] = Wb[tid + p * 256];
    if (tid < NOUT) bbs[tid] = bb[tid];

    #pragma unroll
    for (int p = 0; p < 4; p++) {
        int e  = tid + p * 256;
        int tok = e >> 5, n4 = e & 31;
        float4 v = (n4 < 16)
            ? ((const float4*)(g_q + (size_t)(t0 + tok) * HSZ))[n4]
            : ((const float4*)(g_k + (size_t)(t0 + tok) * HSZ))[n4 - 16];
        *(float4*)&sQK[tok][n4 * 4] = v;
    }
    __syncthreads();

    #pragma unroll
    for (int p = 0; p < 2; p++) {
        int e2   = tid + p * 256;
        int tokL = e2 >> 4;
        int o    = e2 & 15;
        float a = bbs[o];
        #pragma unroll 8
        for (int h = 0; h < 64; h++)
            a += sQK[tokL][h] * Wbs[h * NOUT + o];
        g_A[(t0 + tokL) * NOUT + o] = a;
    }
    #pragma unroll
    for (int p = 0; p < 2; p++) {
        int e2   = tid + p * 256;
        int tokL = e2 >> 4;
        int o    = e2 & 15;
        float a = 0.f;
        #pragma unroll 8
        for (int h = 0; h < 64; h++) {
            a += sQK[tokL][64 + h] * (Wbs[(64 + h) * NOUT + o] + Wbs[(192 + h) * NOUT + o]);
            a += sQK[tokL][h]      *  Wbs[(128 + h) * NOUT + o];
        }
        g_E[(t0 + tokL) * NOUT + o] = a;
    }
}

// ---------------------------------------------------------------------------
// Kernel 4: FUSED score + scatter (unchanged).
// ---------------------------------------------------------------------------
__global__ __launch_bounds__(256) void score_scatter_kernel(float* __restrict__ out)
{
    const int bx = blockIdx.x;
    const int by = blockIdx.y;
    if (by > bx) return;
    const int b  = blockIdx.z;

    __shared__ float  qs[64][68];
    __shared__ float  ks[64][68];
    __shared__ float  Ss[64][65];
    __shared__ float4 Es[256];
    __shared__ float4 As[256];

    const int tid = threadIdx.x;
    const float* qb = g_q + (b * LL + by * 64) * HSZ;
    const float* kb = g_k + (b * LL + bx * 64) * HSZ;

    #pragma unroll
    for (int p = 0; p < 16; p++) {
        int e = tid + p * 256;
        int r = e >> 6, h = e & 63;
        qs[h][r] = qb[r * HSZ + h];
        ks[h][r] = kb[r * HSZ + h];
    }
    Es[tid] = ((const float4*)g_E)[(b * LL + bx * 64) * 4 + tid];
    As[tid] = ((const float4*)g_A)[(b * LL + by * 64) * 4 + tid];
    __syncthreads();

    const int m0 = (tid >> 4) * 4;
    const int n0 = (tid & 15) * 4;
    float acc[4][4];
    #pragma unroll
    for (int i = 0; i < 4; i++)
        #pragma unroll
        for (int j = 0; j < 4; j++) acc[i][j] = 0.f;

    #pragma unroll
    for (int h = 0; h < 64; h++) {
        float4 a = *(const float4*)&qs[h][m0];
        float4 v = *(const float4*)&ks[h][n0];
        float am[4] = {a.x, a.y, a.z, a.w};
        float vn[4] = {v.x, v.y, v.z, v.w};
        #pragma unroll
        for (int i = 0; i < 4; i++)
            #pragma unroll
            for (int j = 0; j < 4; j++) acc[i][j] += am[i] * vn[j];
    }
    #pragma unroll
    for (int i = 0; i < 4; i++)
        #pragma unroll
        for (int j = 0; j < 4; j++) Ss[m0 + i][n0 + j] = acc[i][j];
    __syncthreads();

    const int j  = tid >> 2;
    const int oq = tid & 3;
    const bool diag = (bx == by);
    const float4 ev = Es[tid];
    float4* out4 = (float4*)out;
    const size_t bbase = (size_t)b * NP;

    #pragma unroll 4
    for (int sl = 0; sl < 64; sl++) {
        int s  = by * 64 + sl;
        int p0 = ((s * (1025 - s)) >> 1) + bx * 64 - s;
        float  sv = Ss[sl][j];
        float4 av = As[(sl << 2) | oq];
        float4 r  = make_float4(sv + av.x + ev.x, sv + av.y + ev.y,
                                sv + av.z + ev.z, sv + av.w + ev.w);
        if (!diag || j >= sl)
            out4[(bbase + p0) * 4 + tid] = r;
    }
}

extern "C" void kernel_launch(void* const* d_in, const int* in_sizes, int n_in,
                              void* d_out, int out_size)
{
    const float* x  = (const float*)d_in[0];
    const float* Wq = (const float*)d_in[1];
    const float* bq = (const float*)d_in[2];
    const float* Wk = (const float*)d_in[3];
    const float* bk = (const float*)d_in[4];
    const float* Wb = (const float*)d_in[5];
    const float* bb = (const float*)d_in[6];
    float* out = (float*)d_out;

    prep_kernel<<<1632, 256>>>(x, Wq, Wk);
    wmma_proj_kernel<<<128, 256>>>(bq, bk);
    reduce_ae_kernel<<<64, 256>>>(bb, Wb);
    dim3 g2(LL / 64, LL / 64, BN);
    score_scatter_kernel<<<g2, 256>>>(out);
}

// round 14
// speedup vs baseline: 1.0305x; 1.0305x over previous
#include <cuda_runtime.h>
#include <cuda_bf16.h>
#include <mma.h>
#include <cstdint>

using namespace nvcuda;

#define BN   4
#define LL   512
#define HH   768
#define HSZ  64
#define NOUT 16
#define NTOK (BN*LL)      // 2048
#define NP   131328       // L*(L+1)/2

// scratch (allocation-free rule: __device__ globals)
__device__ __align__(16) __nv_bfloat16 g_xhi[NTOK*HH];   // 3 MB
__device__ __align__(16) __nv_bfloat16 g_xlo[NTOK*HH];   // 3 MB
__device__ __align__(16) __nv_bfloat16 g_whi[HH*128];    // 192 KB  [k][n] n<64:Wq else Wk
__device__ __align__(16) __nv_bfloat16 g_wlo[HH*128];    // 192 KB
__device__ float g_part2[2*NTOK*128];  // 2 MB split-K partials [kh][tok][n]
__device__ float g_q[NTOK*HSZ];        // 512 KB
__device__ float g_k[NTOK*HSZ];        // 512 KB
__device__ float g_A[NTOK*NOUT];       // 128 KB
__device__ float g_E[NTOK*NOUT];       // 128 KB

// ---------------------------------------------------------------------------
// Kernel 1: prep — bf16 hi/lo images of X [tok][k] and W [k][n] (n<64 Wq).
// Blocks [0,1536): X, [1536,1632): W.
// ---------------------------------------------------------------------------
__global__ __launch_bounds__(256) void prep_kernel(
    const float* __restrict__ x,
    const float* __restrict__ Wq,
    const float* __restrict__ Wk)
{
    const int gid = blockIdx.x * 256 + threadIdx.x;
    if (blockIdx.x < 1536) {
        size_t idx = (size_t)gid * 4;
        float4 v = *(const float4*)&x[idx];
        float f[4] = {v.x, v.y, v.z, v.w};
        unsigned short h[4], l[4];
        #pragma unroll
        for (int i = 0; i < 4; i++) {
            __nv_bfloat16 hb = __float2bfloat16(f[i]);
            __nv_bfloat16 lb = __float2bfloat16(f[i] - __bfloat162float(hb));
            h[i] = __bfloat16_as_ushort(hb);
            l[i] = __bfloat16_as_ushort(lb);
        }
        *(uint2*)&g_xhi[idx] = make_uint2((uint32_t)h[0] | ((uint32_t)h[1] << 16),
                                          (uint32_t)h[2] | ((uint32_t)h[3] << 16));
        *(uint2*)&g_xlo[idx] = make_uint2((uint32_t)l[0] | ((uint32_t)l[1] << 16),
                                          (uint32_t)l[2] | ((uint32_t)l[3] << 16));
    } else {
        int id = gid - 1536 * 256;            // 0..24575
        int k  = id >> 5;
        int n  = (id & 31) * 4;
        unsigned short h[4], l[4];
        #pragma unroll
        for (int i = 0; i < 4; i++) {
            int nn = n + i;
            float s = (nn < 64) ? Wq[(size_t)k * HSZ + nn]
                                : Wk[(size_t)k * HSZ + (nn - 64)];
            __nv_bfloat16 hb = __float2bfloat16(s);
            __nv_bfloat16 lb = __float2bfloat16(s - __bfloat162float(hb));
            h[i] = __bfloat16_as_ushort(hb);
            l[i] = __bfloat16_as_ushort(lb);
        }
        size_t o = (size_t)k * 128 + n;
        *(uint2*)&g_whi[o] = make_uint2((uint32_t)h[0] | ((uint32_t)h[1] << 16),
                                        (uint32_t)h[2] | ((uint32_t)h[3] << 16));
        *(uint2*)&g_wlo[o] = make_uint2((uint32_t)l[0] | ((uint32_t)l[1] << 16),
                                        (uint32_t)l[2] | ((uint32_t)l[3] << 16));
    }
}

// ---------------------------------------------------------------------------
// Kernel 2: WMMA bf16 split GEMM with split-K x2.
// Grid = 64 token-tiles x 2 col-halves x 2 K-halves = 256 blocks.
// Block tile 32 tok x 64 cols, K = 384 per block (6 chunks of 64).
// 8 warps 2(m)x4(n), warp tile 16x16. Partials (no bias) -> g_part2.
// ---------------------------------------------------------------------------
__global__ __launch_bounds__(256) void wmma_proj_kernel()
{
    __shared__ __nv_bfloat16 Ah[32][80], Al[32][80];
    __shared__ __nv_bfloat16 Bh[64][80], Bl[64][80];
    __shared__ float Cs[32][80];

    const int tid  = threadIdx.x;
    const int warp = tid >> 5;
    const int bi   = blockIdx.x;
    const int tt   = bi & 63;             // token tile (32 tokens)
    const int cc   = (bi >> 6) & 1;       // col half
    const int kh   = bi >> 7;             // K half
    const int t0   = tt * 32;

    const int m0 = (warp & 1) * 16;
    const int n0 = (warp >> 1) * 16;

    wmma::fragment<wmma::accumulator, 16, 16, 16, float> acc;
    wmma::fill_fragment(acc, 0.f);

    for (int c = 0; c < 6; c++) {
        const int k0 = kh * 384 + c * 64;
        __syncthreads();
        #pragma unroll
        for (int p = 0; p < 2; p++) {
            int e = tid + p * 256;
            int r = e >> 4, q = (e & 15) * 4;
            size_t go = (size_t)(t0 + r) * HH + k0 + q;
            *(uint2*)&Ah[r][q] = *(const uint2*)&g_xhi[go];
            *(uint2*)&Al[r][q] = *(const uint2*)&g_xlo[go];
        }
        #pragma unroll
        for (int p = 0; p < 4; p++) {
            int e = tid + p * 256;
            int r = e >> 4, q = (e & 15) * 4;
            size_t go = (size_t)(k0 + r) * 128 + cc * 64 + q;
            *(uint2*)&Bh[r][q] = *(const uint2*)&g_whi[go];
            *(uint2*)&Bl[r][q] = *(const uint2*)&g_wlo[go];
        }
        __syncthreads();

        #pragma unroll
        for (int ks = 0; ks < 4; ks++) {
            wmma::fragment<wmma::matrix_a, 16, 16, 16, __nv_bfloat16, wmma::row_major> ah, al;
            wmma::fragment<wmma::matrix_b, 16, 16, 16, __nv_bfloat16, wmma::row_major> bh, bl;
            wmma::load_matrix_sync(ah, &Ah[m0][ks * 16], 80);
            wmma::load_matrix_sync(al, &Al[m0][ks * 16], 80);
            wmma::load_matrix_sync(bh, &Bh[ks * 16][n0], 80);
            wmma::load_matrix_sync(bl, &Bl[ks * 16][n0], 80);
            wmma::mma_sync(acc, ah, bh, acc);
            wmma::mma_sync(acc, ah, bl, acc);
            wmma::mma_sync(acc, al, bh, acc);
        }
    }

    __syncthreads();
    wmma::store_matrix_sync(&Cs[m0][n0], acc, 80, wmma::mem_row_major);
    __syncthreads();

    float* dst = g_part2 + ((size_t)kh * NTOK + t0) * 128 + cc * 64;
    #pragma unroll
    for (int p = 0; p < 8; p++) {
        int e = tid + p * 256;             // 0..2047
        int r = e >> 6, col = e & 63;
        dst[(size_t)r * 128 + col] = Cs[r][col];
    }
}

// ---------------------------------------------------------------------------
// Kernel 3: merge split-K partials + bias -> g_q/g_k, then A/E tables.
// A[s,o] = q[s]@Wb[0:64] + bb
// E[e,o] = k[e]@(Wb[64:128]+Wb[192:256]) + q[e]@Wb[128:192]
// ---------------------------------------------------------------------------
__global__ __launch_bounds__(256) void reduce_ae_kernel(
    const float* __restrict__ bq, const float* __restrict__ bk,
    const float* __restrict__ bb, const float* __restrict__ Wb)
{
    __shared__ float Wbs[256 * NOUT];
    __shared__ float sQK[32][132];
    __shared__ float bbs[NOUT];
    __shared__ float bqs[HSZ], bks[HSZ];

    const int tid = threadIdx.x;
    const int t0  = blockIdx.x * 32;

    #pragma unroll
    for (int p = 0; p < 16; p++)
        Wbs[tid + p * 256] = Wb[tid + p * 256];
    if (tid < NOUT) bbs[tid] = bb[tid];
    if (tid < HSZ)  { bqs[tid] = bq[tid]; bks[tid] = bk[tid]; }
    __syncthreads();

    const float4* gp4 = (const float4*)g_part2;
    #pragma unroll
    for (int p = 0; p < 4; p++) {
        int e  = tid + p * 256;
        int tok = e >> 5, n4 = e & 31;
        size_t gi = (size_t)(t0 + tok) * 32 + n4;
        float4 a = gp4[gi];
        float4 bpart = gp4[(size_t)NTOK * 32 + gi];
        float4 v = make_float4(a.x + bpart.x, a.y + bpart.y, a.z + bpart.z, a.w + bpart.w);
        int n = n4 * 4;
        if (n < 64) { v.x += bqs[n]; v.y += bqs[n+1]; v.z += bqs[n+2]; v.w += bqs[n+3]; }
        else        { v.x += bks[n-64]; v.y += bks[n-63]; v.z += bks[n-62]; v.w += bks[n-61]; }
        *(float4*)&sQK[tok][n] = v;
        int tok_g = t0 + tok;
        if (n4 < 16) ((float4*)(g_q + (size_t)tok_g * HSZ))[n4]      = v;
        else         ((float4*)(g_k + (size_t)tok_g * HSZ))[n4 - 16] = v;
    }
    __syncthreads();

    #pragma unroll
    for (int p = 0; p < 2; p++) {
        int e2   = tid + p * 256;
        int tokL = e2 >> 4;
        int o    = e2 & 15;
        float a = bbs[o];
        #pragma unroll 8
        for (int h = 0; h < 64; h++)
            a += sQK[tokL][h] * Wbs[h * NOUT + o];
        g_A[(t0 + tokL) * NOUT + o] = a;
    }
    #pragma unroll
    for (int p = 0; p < 2; p++) {
        int e2   = tid + p * 256;
        int tokL = e2 >> 4;
        int o    = e2 & 15;
        float a = 0.f;
        #pragma unroll 8
        for (int h = 0; h < 64; h++) {
            a += sQK[tokL][64 + h] * (Wbs[(64 + h) * NOUT + o] + Wbs[(192 + h) * NOUT + o]);
            a += sQK[tokL][h]      *  Wbs[(128 + h) * NOUT + o];
        }
        g_E[(t0 + tokL) * NOUT + o] = a;
    }
}

// ---------------------------------------------------------------------------
// Kernel 4: FUSED score + scatter, 512 threads + smem aliasing.
// Compute goes to registers; after sync, the S tile overlays the dead qs
// region (smem 60 -> 43 KB, 16 warps). Store loop covers 2 s-rows at once.
// ---------------------------------------------------------------------------
__global__ __launch_bounds__(512) void score_scatter_kernel(float* __restrict__ out)
{
    const int bx = blockIdx.x;   // e tile
    const int by = blockIdx.y;   // s tile
    if (by > bx) return;
    const int b  = blockIdx.z;

    __shared__ float  buf[2 * 64 * 68];   // qs | ks ; Ss later aliases qs region
    __shared__ float4 Es[256], As[256];
    float* qs = buf;                       // [h][r] stride 68
    float* ks = buf + 64 * 68;

    const int tid = threadIdx.x;
    const float* qb = g_q + (size_t)(b * LL + by * 64) * HSZ;
    const float* kb = g_k + (size_t)(b * LL + bx * 64) * HSZ;

    #pragma unroll
    for (int p = 0; p < 8; p++) {
        int e = tid + p * 512;
        int r = e >> 6, h = e & 63;
        qs[h * 68 + r] = qb[r * HSZ + h];
        ks[h * 68 + r] = kb[r * HSZ + h];
    }
    if (tid < 256) Es[tid]       = ((const float4*)g_E)[(b * LL + bx * 64) * 4 + tid];
    else           As[tid - 256] = ((const float4*)g_A)[(b * LL + by * 64) * 4 + (tid - 256)];
    __syncthreads();

    // compute: thread tile 2(m) x 4(n)
    const int m0 = (tid >> 4) * 2;
    const int n0 = (tid & 15) * 4;
    float acc[2][4];
    #pragma unroll
    for (int i = 0; i < 2; i++)
        #pragma unroll
        for (int j = 0; j < 4; j++) acc[i][j] = 0.f;

    #pragma unroll
    for (int h = 0; h < 64; h++) {
        float  a0 = qs[h * 68 + m0];
        float  a1 = qs[h * 68 + m0 + 1];
        float4 v  = *(const float4*)&ks[h * 68 + n0];
        acc[0][0] += a0 * v.x; acc[0][1] += a0 * v.y; acc[0][2] += a0 * v.z; acc[0][3] += a0 * v.w;
        acc[1][0] += a1 * v.x; acc[1][1] += a1 * v.y; acc[1][2] += a1 * v.z; acc[1][3] += a1 * v.w;
    }
    __syncthreads();                       // all qs reads done
    float* Ss = buf;                       // [sl][j] stride 65 (aliases qs)
    #pragma unroll
    for (int i = 0; i < 2; i++)
        #pragma unroll
        for (int j = 0; j < 4; j++) Ss[(m0 + i) * 65 + n0 + j] = acc[i][j];
    __syncthreads();

    // store: 512 threads = 2 s-rows x (64 j x 4 oq)
    const int lane = tid & 255;
    const int jj   = lane >> 2;
    const int oq   = tid & 3;
    const int slh  = tid >> 8;             // 0/1
    const bool diag = (bx == by);
    const float4 ev = Es[lane];
    float4* out4 = (float4*)out;
    const size_t bbase = (size_t)b * NP;

    #pragma unroll 4
    for (int sl2 = 0; sl2 < 32; sl2++) {
        int sl = sl2 * 2 + slh;
        int s  = by * 64 + sl;
        int p0 = ((s * (1025 - s)) >> 1) + bx * 64 - s;
        float  sv = Ss[sl * 65 + jj];
        float4 av = As[(sl << 2) | oq];
        float4 r  = make_float4(sv + av.x + ev.x, sv + av.y + ev.y,
                                sv + av.z + ev.z, sv + av.w + ev.w);
        if (!diag || jj >= sl)
            out4[(bbase + p0) * 4 + lane] = r;
    }
}

extern "C" void kernel_launch(void* const* d_in, const int* in_sizes, int n_in,
                              void* d_out, int out_size)
{
    const float* x  = (const float*)d_in[0];
    const float* Wq = (const float*)d_in[1];
    const float* bq = (const float*)d_in[2];
    const float* Wk = (const float*)d_in[3];
    const float* bk = (const float*)d_in[4];
    const float* Wb = (const float*)d_in[5];
    const float* bb = (const float*)d_in[6];
    float* out = (float*)d_out;

    prep_kernel<<<1632, 256>>>(x, Wq, Wk);
    wmma_proj_kernel<<<256, 256>>>();
    reduce_ae_kernel<<<64, 256>>>(bq, bk, bb, Wb);
    dim3 g2(LL / 64, LL / 64, BN);
    score_scatter_kernel<<<g2, 512>>>(out);
}

// round 15
// speedup vs baseline: 1.0687x; 1.0370x over previous
#include <cuda_runtime.h>
#include <cuda_bf16.h>
#include <mma.h>
#include <cstdint>

using namespace nvcuda;
typedef unsigned long long u64;

#define BN   4
#define LL   512
#define HH   768
#define HSZ  64
#define NOUT 16
#define NTOK (BN*LL)      // 2048
#define NP   131328       // L*(L+1)/2

// scratch (allocation-free rule: __device__ globals)
__device__ __align__(16) __nv_bfloat16 g_whi[HH*128];    // 192 KB [k][n] n<64:Wq else Wk
__device__ __align__(16) __nv_bfloat16 g_wlo[HH*128];    // 192 KB
__device__ float g_part2[2*NTOK*128];  // 2 MB split-K partials [kh][tok][n]
__device__ float g_q[NTOK*HSZ];        // 512 KB
__device__ float g_k[NTOK*HSZ];        // 512 KB
__device__ float g_A[NTOK*NOUT];       // 128 KB
__device__ float g_E[NTOK*NOUT];       // 128 KB

__device__ __forceinline__ u64 pk2s(float v) {
    u64 r; asm("mov.b64 %0, {%1, %1};" : "=l"(r) : "f"(v)); return r;
}
__device__ __forceinline__ u64 addf2(u64 a, u64 b) {
    u64 d; asm("add.rn.f32x2 %0, %1, %2;" : "=l"(d) : "l"(a), "l"(b)); return d;
}

// ---------------------------------------------------------------------------
// Kernel 1: W prep only — bf16 hi/lo images of W [k][n] (n<64 Wq else Wk).
// 96 blocks x 256 threads = 24576 = 768k x 32 quads.
// ---------------------------------------------------------------------------
__global__ __launch_bounds__(256) void prep_w_kernel(
    const float* __restrict__ Wq, const float* __restrict__ Wk)
{
    const int id = blockIdx.x * 256 + threadIdx.x;   // 0..24575
    const int k  = id >> 5;
    const int n  = (id & 31) * 4;
    unsigned short h[4], l[4];
    #pragma unroll
    for (int i = 0; i < 4; i++) {
        int nn = n + i;
        float s = (nn < 64) ? Wq[(size_t)k * HSZ + nn]
                            : Wk[(size_t)k * HSZ + (nn - 64)];
        __nv_bfloat16 hb = __float2bfloat16(s);
        __nv_bfloat16 lb = __float2bfloat16(s - __bfloat162float(hb));
        h[i] = __bfloat16_as_ushort(hb);
        l[i] = __bfloat16_as_ushort(lb);
    }
    size_t o = (size_t)k * 128 + n;
    *(uint2*)&g_whi[o] = make_uint2((uint32_t)h[0] | ((uint32_t)h[1] << 16),
                                    (uint32_t)h[2] | ((uint32_t)h[3] << 16));
    *(uint2*)&g_wlo[o] = make_uint2((uint32_t)l[0] | ((uint32_t)l[1] << 16),
                                    (uint32_t)l[2] | ((uint32_t)l[3] << 16));
}

// ---------------------------------------------------------------------------
// Kernel 2: WMMA bf16 split GEMM, X converted inline during staging.
// Grid = 64 token-tiles x 2 col-halves x 2 K-halves = 256 blocks.
// Block tile 32 tok x 64 cols, K = 384 per block (6 chunks of 64).
// 8 warps 2(m)x4(n), warp tile 16x16. Partials (no bias) -> g_part2.
// ---------------------------------------------------------------------------
__global__ __launch_bounds__(256) void wmma_proj_kernel(const float* __restrict__ x)
{
    __shared__ __nv_bfloat16 Ah[32][80], Al[32][80];
    __shared__ __nv_bfloat16 Bh[64][80], Bl[64][80];
    __shared__ float Cs[32][80];

    const int tid  = threadIdx.x;
    const int warp = tid >> 5;
    const int bi   = blockIdx.x;
    const int tt   = bi & 63;             // token tile (32 tokens)
    const int cc   = (bi >> 6) & 1;       // col half
    const int kh   = bi >> 7;             // K half
    const int t0   = tt * 32;

    const int m0 = (warp & 1) * 16;
    const int n0 = (warp >> 1) * 16;

    wmma::fragment<wmma::accumulator, 16, 16, 16, float> acc;
    wmma::fill_fragment(acc, 0.f);

    for (int c = 0; c < 6; c++) {
        const int k0 = kh * 384 + c * 64;
        __syncthreads();
        // stage A: load fp32 x, convert to hi/lo inline (32 rows x 16 quads)
        #pragma unroll
        for (int p = 0; p < 2; p++) {
            int e = tid + p * 256;         // 0..511
            int r = e >> 4, q = (e & 15) * 4;
            float4 v = *(const float4*)&x[(size_t)(t0 + r) * HH + k0 + q];
            float f[4] = {v.x, v.y, v.z, v.w};
            unsigned short h[4], l[4];
            #pragma unroll
            for (int i = 0; i < 4; i++) {
                __nv_bfloat16 hb = __float2bfloat16(f[i]);
                __nv_bfloat16 lb = __float2bfloat16(f[i] - __bfloat162float(hb));
                h[i] = __bfloat16_as_ushort(hb);
                l[i] = __bfloat16_as_ushort(lb);
            }
            *(uint2*)&Ah[r][q] = make_uint2((uint32_t)h[0] | ((uint32_t)h[1] << 16),
                                            (uint32_t)h[2] | ((uint32_t)h[3] << 16));
            *(uint2*)&Al[r][q] = make_uint2((uint32_t)l[0] | ((uint32_t)l[1] << 16),
                                            (uint32_t)l[2] | ((uint32_t)l[3] << 16));
        }
        // stage B hi/lo from prepped images (64 rows x 16 quads)
        #pragma unroll
        for (int p = 0; p < 4; p++) {
            int e = tid + p * 256;         // 0..1023
            int r = e >> 4, q = (e & 15) * 4;
            size_t go = (size_t)(k0 + r) * 128 + cc * 64 + q;
            *(uint2*)&Bh[r][q] = *(const uint2*)&g_whi[go];
            *(uint2*)&Bl[r][q] = *(const uint2*)&g_wlo[go];
        }
        __syncthreads();

        #pragma unroll
        for (int ks = 0; ks < 4; ks++) {
            wmma::fragment<wmma::matrix_a, 16, 16, 16, __nv_bfloat16, wmma::row_major> ah, al;
            wmma::fragment<wmma::matrix_b, 16, 16, 16, __nv_bfloat16, wmma::row_major> bh, bl;
            wmma::load_matrix_sync(ah, &Ah[m0][ks * 16], 80);
            wmma::load_matrix_sync(al, &Al[m0][ks * 16], 80);
            wmma::load_matrix_sync(bh, &Bh[ks * 16][n0], 80);
            wmma::load_matrix_sync(bl, &Bl[ks * 16][n0], 80);
            wmma::mma_sync(acc, ah, bh, acc);
            wmma::mma_sync(acc, ah, bl, acc);
            wmma::mma_sync(acc, al, bh, acc);
        }
    }

    __syncthreads();
    wmma::store_matrix_sync(&Cs[m0][n0], acc, 80, wmma::mem_row_major);
    __syncthreads();

    float* dst = g_part2 + ((size_t)kh * NTOK + t0) * 128 + cc * 64;
    #pragma unroll
    for (int p = 0; p < 8; p++) {
        int e = tid + p * 256;             // 0..2047
        int r = e >> 6, col = e & 63;
        dst[(size_t)r * 128 + col] = Cs[r][col];
    }
}

// ---------------------------------------------------------------------------
// Kernel 3: merge split-K partials + bias -> g_q/g_k, then A/E tables.
// A[s,o] = q[s]@Wb[0:64] + bb
// E[e,o] = k[e]@(Wb[64:128]+Wb[192:256]) + q[e]@Wb[128:192]
// ---------------------------------------------------------------------------
__global__ __launch_bounds__(256) void reduce_ae_kernel(
    const float* __restrict__ bq, const float* __restrict__ bk,
    const float* __restrict__ bb, const float* __restrict__ Wb)
{
    __shared__ float Wbs[256 * NOUT];
    __shared__ float sQK[32][132];
    __shared__ float bbs[NOUT];
    __shared__ float bqs[HSZ], bks[HSZ];

    const int tid = threadIdx.x;
    const int t0  = blockIdx.x * 32;

    #pragma unroll
    for (int p = 0; p < 16; p++)
        Wbs[tid + p * 256] = Wb[tid + p * 256];
    if (tid < NOUT) bbs[tid] = bb[tid];
    if (tid < HSZ)  { bqs[tid] = bq[tid]; bks[tid] = bk[tid]; }
    __syncthreads();

    const float4* gp4 = (const float4*)g_part2;
    #pragma unroll
    for (int p = 0; p < 4; p++) {
        int e  = tid + p * 256;
        int tok = e >> 5, n4 = e & 31;
        size_t gi = (size_t)(t0 + tok) * 32 + n4;
        float4 a = gp4[gi];
        float4 bpart = gp4[(size_t)NTOK * 32 + gi];
        float4 v = make_float4(a.x + bpart.x, a.y + bpart.y, a.z + bpart.z, a.w + bpart.w);
        int n = n4 * 4;
        if (n < 64) { v.x += bqs[n]; v.y += bqs[n+1]; v.z += bqs[n+2]; v.w += bqs[n+3]; }
        else        { v.x += bks[n-64]; v.y += bks[n-63]; v.z += bks[n-62]; v.w += bks[n-61]; }
        *(float4*)&sQK[tok][n] = v;
        int tok_g = t0 + tok;
        if (n4 < 16) ((float4*)(g_q + (size_t)tok_g * HSZ))[n4]      = v;
        else         ((float4*)(g_k + (size_t)tok_g * HSZ))[n4 - 16] = v;
    }
    __syncthreads();

    #pragma unroll
    for (int p = 0; p < 2; p++) {
        int e2   = tid + p * 256;
        int tokL = e2 >> 4;
        int o    = e2 & 15;
        float a = bbs[o];
        #pragma unroll 8
        for (int h = 0; h < 64; h++)
            a += sQK[tokL][h] * Wbs[h * NOUT + o];
        g_A[(t0 + tokL) * NOUT + o] = a;
    }
    #pragma unroll
    for (int p = 0; p < 2; p++) {
        int e2   = tid + p * 256;
        int tokL = e2 >> 4;
        int o    = e2 & 15;
        float a = 0.f;
        #pragma unroll 8
        for (int h = 0; h < 64; h++) {
            a += sQK[tokL][64 + h] * (Wbs[(64 + h) * NOUT + o] + Wbs[(192 + h) * NOUT + o]);
            a += sQK[tokL][h]      *  Wbs[(128 + h) * NOUT + o];
        }
        g_E[(t0 + tokL) * NOUT + o] = a;
    }
}

// ---------------------------------------------------------------------------
// Kernel 4: FUSED score + scatter; store loop in packed f32x2 adds
// (4 add.f32x2 + 1 mov replace 8 FADD per float4 -> fewer issue slots).
// ---------------------------------------------------------------------------
__global__ __launch_bounds__(512) void score_scatter_kernel(float* __restrict__ out)
{
    const int bx = blockIdx.x;   // e tile
    const int by = blockIdx.y;   // s tile
    if (by > bx) return;
    const int b  = blockIdx.z;

    __shared__ float buf[2 * 64 * 68];    // qs | ks ; Ss later aliases qs region
    __shared__ __align__(16) float4 Es[256], As[256];
    float* qs = buf;                       // [h][r] stride 68
    float* ks = buf + 64 * 68;

    const int tid = threadIdx.x;
    const float* qb = g_q + (size_t)(b * LL + by * 64) * HSZ;
    const float* kb = g_k + (size_t)(b * LL + bx * 64) * HSZ;

    #pragma unroll
    for (int p = 0; p < 8; p++) {
        int e = tid + p * 512;
        int r = e >> 6, h = e & 63;
        qs[h * 68 + r] = qb[r * HSZ + h];
        ks[h * 68 + r] = kb[r * HSZ + h];
    }
    if (tid < 256) Es[tid]       = ((const float4*)g_E)[(b * LL + bx * 64) * 4 + tid];
    else           As[tid - 256] = ((const float4*)g_A)[(b * LL + by * 64) * 4 + (tid - 256)];
    __syncthreads();

    // compute: thread tile 2(m) x 4(n)
    const int m0 = (tid >> 4) * 2;
    const int n0 = (tid & 15) * 4;
    float acc[2][4];
    #pragma unroll
    for (int i = 0; i < 2; i++)
        #pragma unroll
        for (int j = 0; j < 4; j++) acc[i][j] = 0.f;

    #pragma unroll
    for (int h = 0; h < 64; h++) {
        float  a0 = qs[h * 68 + m0];
        float  a1 = qs[h * 68 + m0 + 1];
        float4 v  = *(const float4*)&ks[h * 68 + n0];
        acc[0][0] += a0 * v.x; acc[0][1] += a0 * v.y; acc[0][2] += a0 * v.z; acc[0][3] += a0 * v.w;
        acc[1][0] += a1 * v.x; acc[1][1] += a1 * v.y; acc[1][2] += a1 * v.z; acc[1][3] += a1 * v.w;
    }
    __syncthreads();                       // all qs reads done
    float* Ss = buf;                       // [sl][j] stride 65 (aliases qs)
    #pragma unroll
    for (int i = 0; i < 2; i++)
        #pragma unroll
        for (int j = 0; j < 4; j++) Ss[(m0 + i) * 65 + n0 + j] = acc[i][j];
    __syncthreads();

    // store: 512 threads = 2 s-rows x (64 j x 4 oq); packed f32x2 math
    const int lane = tid & 255;
    const int jj   = lane >> 2;
    const int oq   = tid & 3;
    const int slh  = tid >> 8;             // 0/1
    const bool diag = (bx == by);
    const ulonglong2 ev2 = ((const ulonglong2*)Es)[lane];
    ulonglong2* out2 = (ulonglong2*)out;
    const size_t bbase = (size_t)b * NP;
    const ulonglong2* As2 = (const ulonglong2*)As;

    #pragma unroll 4
    for (int sl2 = 0; sl2 < 32; sl2++) {
        int sl = sl2 * 2 + slh;
        int s  = by * 64 + sl;
        int p0 = ((s * (1025 - s)) >> 1) + bx * 64 - s;
        u64 sv2 = pk2s(Ss[sl * 65 + jj]);
        ulonglong2 av2 = As2[(sl << 2) | oq];
        ulonglong2 r;
        r.x = addf2(addf2(av2.x, ev2.x), sv2);
        r.y = addf2(addf2(av2.y, ev2.y), sv2);
        if (!diag || jj >= sl)
            out2[(bbase + p0) * 4 + lane] = r;
    }
}

extern "C" void kernel_launch(void* const* d_in, const int* in_sizes, int n_in,
                              void* d_out, int out_size)
{
    const float* x  = (const float*)d_in[0];
    const float* Wq = (const float*)d_in[1];
    const float* bq = (const float*)d_in[2];
    const float* Wk = (const float*)d_in[3];
    const float* bk = (const float*)d_in[4];
    const float* Wb = (const float*)d_in[5];
    const float* bb = (const float*)d_in[6];
    float* out = (float*)d_out;

    prep_w_kernel<<<96, 256>>>(Wq, Wk);
    wmma_proj_kernel<<<256, 256>>>(x);
    reduce_ae_kernel<<<64, 256>>>(bq, bk, bb, Wb);
    dim3 g2(LL / 64, LL / 64, BN);
    score_scatter_kernel<<<g2, 512>>>(out);
}

// round 16
// speedup vs baseline: 1.1160x; 1.0443x over previous
#include <cuda_runtime.h>
#include <cuda_bf16.h>
#include <mma.h>
#include <cstdint>

using namespace nvcuda;

#define BN   4
#define LL   512
#define HH   768
#define HSZ  64
#define NOUT 16
#define NTOK (BN*LL)      // 2048
#define NP   131328       // L*(L+1)/2

// scratch (allocation-free rule: __device__ globals)
__device__ __align__(16) __nv_bfloat16 g_whi[HH*128];    // 192 KB [k][n] n<64:Wq else Wk
__device__ __align__(16) __nv_bfloat16 g_wlo[HH*128];    // 192 KB
__device__ float g_part2[2*NTOK*128];  // 2 MB split-K partials [kh][tok][n]
__device__ float g_q[NTOK*HSZ];        // 512 KB
__device__ float g_k[NTOK*HSZ];        // 512 KB
__device__ float g_A[NTOK*NOUT];       // 128 KB
__device__ float g_E[NTOK*NOUT];       // 128 KB

// ---------------------------------------------------------------------------
// Kernel 1: W prep — bf16 hi/lo images of W [k][n] (n<64 Wq else Wk).
// ---------------------------------------------------------------------------
__global__ __launch_bounds__(256) void prep_w_kernel(
    const float* __restrict__ Wq, const float* __restrict__ Wk)
{
    const int id = blockIdx.x * 256 + threadIdx.x;   // 0..24575
    const int k  = id >> 5;
    const int n  = (id & 31) * 4;
    unsigned short h[4], l[4];
    #pragma unroll
    for (int i = 0; i < 4; i++) {
        int nn = n + i;
        float s = (nn < 64) ? Wq[(size_t)k * HSZ + nn]
                            : Wk[(size_t)k * HSZ + (nn - 64)];
        __nv_bfloat16 hb = __float2bfloat16(s);
        __nv_bfloat16 lb = __float2bfloat16(s - __bfloat162float(hb));
        h[i] = __bfloat16_as_ushort(hb);
        l[i] = __bfloat16_as_ushort(lb);
    }
    size_t o = (size_t)k * 128 + n;
    *(uint2*)&g_whi[o] = make_uint2((uint32_t)h[0] | ((uint32_t)h[1] << 16),
                                    (uint32_t)h[2] | ((uint32_t)h[3] << 16));
    *(uint2*)&g_wlo[o] = make_uint2((uint32_t)l[0] | ((uint32_t)l[1] << 16),
                                    (uint32_t)l[2] | ((uint32_t)l[3] << 16));
}

// ---------------------------------------------------------------------------
// Kernel 2: WMMA bf16 split GEMM, X converted inline during staging.
// Grid = 64 token-tiles x 2 col-halves x 2 K-halves = 256 blocks.
// ---------------------------------------------------------------------------
__global__ __launch_bounds__(256) void wmma_proj_kernel(const float* __restrict__ x)
{
    __shared__ __nv_bfloat16 Ah[32][80], Al[32][80];
    __shared__ __nv_bfloat16 Bh[64][80], Bl[64][80];
    __shared__ float Cs[32][80];

    const int tid  = threadIdx.x;
    const int warp = tid >> 5;
    const int bi   = blockIdx.x;
    const int tt   = bi & 63;
    const int cc   = (bi >> 6) & 1;
    const int kh   = bi >> 7;
    const int t0   = tt * 32;

    const int m0 = (warp & 1) * 16;
    const int n0 = (warp >> 1) * 16;

    wmma::fragment<wmma::accumulator, 16, 16, 16, float> acc;
    wmma::fill_fragment(acc, 0.f);

    for (int c = 0; c < 6; c++) {
        const int k0 = kh * 384 + c * 64;
        __syncthreads();
        #pragma unroll
        for (int p = 0; p < 2; p++) {
            int e = tid + p * 256;
            int r = e >> 4, q = (e & 15) * 4;
            float4 v = *(const float4*)&x[(size_t)(t0 + r) * HH + k0 + q];
            float f[4] = {v.x, v.y, v.z, v.w};
            unsigned short h[4], l[4];
            #pragma unroll
            for (int i = 0; i < 4; i++) {
                __nv_bfloat16 hb = __float2bfloat16(f[i]);
                __nv_bfloat16 lb = __float2bfloat16(f[i] - __bfloat162float(hb));
                h[i] = __bfloat16_as_ushort(hb);
                l[i] = __bfloat16_as_ushort(lb);
            }
            *(uint2*)&Ah[r][q] = make_uint2((uint32_t)h[0] | ((uint32_t)h[1] << 16),
                                            (uint32_t)h[2] | ((uint32_t)h[3] << 16));
            *(uint2*)&Al[r][q] = make_uint2((uint32_t)l[0] | ((uint32_t)l[1] << 16),
                                            (uint32_t)l[2] | ((uint32_t)l[3] << 16));
        }
        #pragma unroll
        for (int p = 0; p < 4; p++) {
            int e = tid + p * 256;
            int r = e >> 4, q = (e & 15) * 4;
            size_t go = (size_t)(k0 + r) * 128 + cc * 64 + q;
            *(uint2*)&Bh[r][q] = *(const uint2*)&g_whi[go];
            *(uint2*)&Bl[r][q] = *(const uint2*)&g_wlo[go];
        }
        __syncthreads();

        #pragma unroll
        for (int ks = 0; ks < 4; ks++) {
            wmma::fragment<wmma::matrix_a, 16, 16, 16, __nv_bfloat16, wmma::row_major> ah, al;
            wmma::fragment<wmma::matrix_b, 16, 16, 16, __nv_bfloat16, wmma::row_major> bh, bl;
            wmma::load_matrix_sync(ah, &Ah[m0][ks * 16], 80);
            wmma::load_matrix_sync(al, &Al[m0][ks * 16], 80);
            wmma::load_matrix_sync(bh, &Bh[ks * 16][n0], 80);
            wmma::load_matrix_sync(bl, &Bl[ks * 16][n0], 80);
            wmma::mma_sync(acc, ah, bh, acc);
            wmma::mma_sync(acc, ah, bl, acc);
            wmma::mma_sync(acc, al, bh, acc);
        }
    }

    __syncthreads();
    wmma::store_matrix_sync(&Cs[m0][n0], acc, 80, wmma::mem_row_major);
    __syncthreads();

    float* dst = g_part2 + ((size_t)kh * NTOK + t0) * 128 + cc * 64;
    #pragma unroll
    for (int p = 0; p < 8; p++) {
        int e = tid + p * 256;
        int r = e >> 6, col = e & 63;
        dst[(size_t)r * 128 + col] = Cs[r][col];
    }
}

// ---------------------------------------------------------------------------
// Kernel 3: merge split-K partials + bias -> g_q/g_k, then A/E tables.
// ---------------------------------------------------------------------------
__global__ __launch_bounds__(256) void reduce_ae_kernel(
    const float* __restrict__ bq, const float* __restrict__ bk,
    const float* __restrict__ bb, const float* __restrict__ Wb)
{
    __shared__ float Wbs[256 * NOUT];
    __shared__ float sQK[32][132];
    __shared__ float bbs[NOUT];
    __shared__ float bqs[HSZ], bks[HSZ];

    const int tid = threadIdx.x;
    const int t0  = blockIdx.x * 32;

    #pragma unroll
    for (int p = 0; p < 16; p++)
        Wbs[tid + p * 256] = Wb[tid + p * 256];
    if (tid < NOUT) bbs[tid] = bb[tid];
    if (tid < HSZ)  { bqs[tid] = bq[tid]; bks[tid] = bk[tid]; }
    __syncthreads();

    const float4* gp4 = (const float4*)g_part2;
    #pragma unroll
    for (int p = 0; p < 4; p++) {
        int e  = tid + p * 256;
        int tok = e >> 5, n4 = e & 31;
        size_t gi = (size_t)(t0 + tok) * 32 + n4;
        float4 a = gp4[gi];
        float4 bpart = gp4[(size_t)NTOK * 32 + gi];
        float4 v = make_float4(a.x + bpart.x, a.y + bpart.y, a.z + bpart.z, a.w + bpart.w);
        int n = n4 * 4;
        if (n < 64) { v.x += bqs[n]; v.y += bqs[n+1]; v.z += bqs[n+2]; v.w += bqs[n+3]; }
        else        { v.x += bks[n-64]; v.y += bks[n-63]; v.z += bks[n-62]; v.w += bks[n-61]; }
        *(float4*)&sQK[tok][n] = v;
        int tok_g = t0 + tok;
        if (n4 < 16) ((float4*)(g_q + (size_t)tok_g * HSZ))[n4]      = v;
        else         ((float4*)(g_k + (size_t)tok_g * HSZ))[n4 - 16] = v;
    }
    __syncthreads();

    #pragma unroll
    for (int p = 0; p < 2; p++) {
        int e2   = tid + p * 256;
        int tokL = e2 >> 4;
        int o    = e2 & 15;
        float a = bbs[o];
        #pragma unroll 8
        for (int h = 0; h < 64; h++)
            a += sQK[tokL][h] * Wbs[h * NOUT + o];
        g_A[(t0 + tokL) * NOUT + o] = a;
    }
    #pragma unroll
    for (int p = 0; p < 2; p++) {
        int e2   = tid + p * 256;
        int tokL = e2 >> 4;
        int o    = e2 & 15;
        float a = 0.f;
        #pragma unroll 8
        for (int h = 0; h < 64; h++) {
            a += sQK[tokL][64 + h] * (Wbs[(64 + h) * NOUT + o] + Wbs[(192 + h) * NOUT + o]);
            a += sQK[tokL][h]      *  Wbs[(128 + h) * NOUT + o];
        }
        g_E[(t0 + tokL) * NOUT + o] = a;
    }
}

// ---------------------------------------------------------------------------
// Kernel 4: FUSED score + scatter, 32x32 pair-tiles for block-level
// parallelism. Grid (16,16,4) = 544 working blocks (~3.7/SM), smem ~17.5 KB
// -> many concurrent blocks hide the load/compute/store latency chain.
// ---------------------------------------------------------------------------
__global__ __launch_bounds__(256) void score_scatter_kernel(float* __restrict__ out)
{
    const int bx = blockIdx.x;   // e tile (32)
    const int by = blockIdx.y;   // s tile (32)
    if (by > bx) return;
    const int b  = blockIdx.z;

    __shared__ float  qs[64][36];   // [h][r] r<32
    __shared__ float  ks[64][36];
    __shared__ float  Ss[32][33];
    __shared__ float4 Es[128];      // 32 e-rows x 4
    __shared__ float4 As[128];      // 32 s-rows x 4

    const int tid = threadIdx.x;
    const float* qb = g_q + (size_t)(b * LL + by * 32) * HSZ;
    const float* kb = g_k + (size_t)(b * LL + bx * 32) * HSZ;

    #pragma unroll
    for (int p = 0; p < 8; p++) {
        int e = tid + p * 256;     // 0..2047 = 32 r x 64 h
        int r = e >> 6, h = e & 63;
        qs[h][r] = qb[r * HSZ + h];
        ks[h][r] = kb[r * HSZ + h];
    }
    if (tid < 128)      Es[tid]       = ((const float4*)g_E)[(b * LL + bx * 32) * 4 + tid];
    else if (tid < 256) As[tid - 128] = ((const float4*)g_A)[(b * LL + by * 32) * 4 + (tid - 128)];
    __syncthreads();

    // compute: 32x32 / 256 threads = 2(m) x 2(n) per thread
    const int m0 = (tid >> 4) * 2;
    const int n0 = (tid & 15) * 2;
    float a00 = 0.f, a01 = 0.f, a10 = 0.f, a11 = 0.f;
    #pragma unroll
    for (int h = 0; h < 64; h++) {
        float q0 = qs[h][m0], q1 = qs[h][m0 + 1];
        float k0 = ks[h][n0], k1 = ks[h][n0 + 1];
        a00 += q0 * k0; a01 += q0 * k1;
        a10 += q1 * k0; a11 += q1 * k1;
    }
    Ss[m0][n0] = a00;     Ss[m0][n0 + 1] = a01;
    Ss[m0 + 1][n0] = a10; Ss[m0 + 1][n0 + 1] = a11;
    __syncthreads();

    // store: 256 threads = 2 s-rows x (32 jj x 4 oq); 16 iterations
    const int lane = tid & 127;
    const int jj   = lane >> 2;
    const int oq   = lane & 3;
    const int slh  = tid >> 7;             // 0/1
    const bool diag = (bx == by);
    const float4 ev = Es[lane];
    float4* out4 = (float4*)out;
    const size_t bbase = (size_t)b * NP;

    #pragma unroll 4
    for (int sl2 = 0; sl2 < 16; sl2++) {
        int sl = sl2 * 2 + slh;
        int s  = by * 32 + sl;
        int p0 = ((s * (1025 - s)) >> 1) + bx * 32 - s;
        float  sv = Ss[sl][jj];
        float4 av = As[(sl << 2) | oq];
        float4 r  = make_float4(sv + av.x + ev.x, sv + av.y + ev.y,
                                sv + av.z + ev.z, sv + av.w + ev.w);
        if (!diag || jj >= sl)
            out4[(bbase + p0) * 4 + lane] = r;
    }
}

extern "C" void kernel_launch(void* const* d_in, const int* in_sizes, int n_in,
                              void* d_out, int out_size)
{
    const float* x  = (const float*)d_in[0];
    const float* Wq = (const float*)d_in[1];
    const float* bq = (const float*)d_in[2];
    const float* Wk = (const float*)d_in[3];
    const float* bk = (const float*)d_in[4];
    const float* Wb = (const float*)d_in[5];
    const float* bb = (const float*)d_in[6];
    float* out = (float*)d_out;

    prep_w_kernel<<<96, 256>>>(Wq, Wk);
    wmma_proj_kernel<<<256, 256>>>(x);
    reduce_ae_kernel<<<64, 256>>>(bq, bk, bb, Wb);
    dim3 g2(LL / 32, LL / 32, BN);
    score_scatter_kernel<<<g2, 256>>>(out);
}

// round 17
// speedup vs baseline: 1.1668x; 1.0455x over previous
#include <cuda_runtime.h>
#include <cuda_bf16.h>
#include <mma.h>
#include <cstdint>

using namespace nvcuda;

#define BN   4
#define LL   512
#define HH   768
#define HSZ  64
#define NOUT 16
#define NTOK (BN*LL)      // 2048
#define NP   131328       // L*(L+1)/2

// scratch (allocation-free rule: __device__ globals)
__device__ __align__(16) __nv_bfloat16 g_whi[HH*128];    // 192 KB [k][n] n<64:Wq else Wk
__device__ __align__(16) __nv_bfloat16 g_wlo[HH*128];    // 192 KB
__device__ float g_part4[4*NTOK*128];  // 4 MB split-K partials [kq][tok][n]
__device__ float g_q[NTOK*HSZ];        // 512 KB
__device__ float g_k[NTOK*HSZ];        // 512 KB
__device__ float g_A[NTOK*NOUT];       // 128 KB
__device__ float g_E[NTOK*NOUT];       // 128 KB

// ---------------------------------------------------------------------------
// Kernel 1: W prep — bf16 hi/lo images of W [k][n] (n<64 Wq else Wk).
// ---------------------------------------------------------------------------
__global__ __launch_bounds__(256) void prep_w_kernel(
    const float* __restrict__ Wq, const float* __restrict__ Wk)
{
    const int id = blockIdx.x * 256 + threadIdx.x;   // 0..24575
    const int k  = id >> 5;
    const int n  = (id & 31) * 4;
    unsigned short h[4], l[4];
    #pragma unroll
    for (int i = 0; i < 4; i++) {
        int nn = n + i;
        float s = (nn < 64) ? Wq[(size_t)k * HSZ + nn]
                            : Wk[(size_t)k * HSZ + (nn - 64)];
        __nv_bfloat16 hb = __float2bfloat16(s);
        __nv_bfloat16 lb = __float2bfloat16(s - __bfloat162float(hb));
        h[i] = __bfloat16_as_ushort(hb);
        l[i] = __bfloat16_as_ushort(lb);
    }
    size_t o = (size_t)k * 128 + n;
    *(uint2*)&g_whi[o] = make_uint2((uint32_t)h[0] | ((uint32_t)h[1] << 16),
                                    (uint32_t)h[2] | ((uint32_t)h[3] << 16));
    *(uint2*)&g_wlo[o] = make_uint2((uint32_t)l[0] | ((uint32_t)l[1] << 16),
                                    (uint32_t)l[2] | ((uint32_t)l[3] << 16));
}

// ---------------------------------------------------------------------------
// Kernel 2: WMMA bf16 split GEMM, split-K x4, X converted inline.
// Grid = 64 token-tiles x 2 col-halves x 4 K-quarters = 512 blocks.
// Block tile 32 tok x 64 cols, K = 192 per block (3 chunks of 64).
// ---------------------------------------------------------------------------
__global__ __launch_bounds__(256) void wmma_proj_kernel(const float* __restrict__ x)
{
    __shared__ __nv_bfloat16 Ah[32][80], Al[32][80];
    __shared__ __nv_bfloat16 Bh[64][80], Bl[64][80];
    __shared__ float Cs[32][80];

    const int tid  = threadIdx.x;
    const int warp = tid >> 5;
    const int bi   = blockIdx.x;
    const int tt   = bi & 63;
    const int cc   = (bi >> 6) & 1;
    const int kq   = bi >> 7;             // 0..3
    const int t0   = tt * 32;

    const int m0 = (warp & 1) * 16;
    const int n0 = (warp >> 1) * 16;

    wmma::fragment<wmma::accumulator, 16, 16, 16, float> acc;
    wmma::fill_fragment(acc, 0.f);

    for (int c = 0; c < 3; c++) {
        const int k0 = kq * 192 + c * 64;
        __syncthreads();
        #pragma unroll
        for (int p = 0; p < 2; p++) {
            int e = tid + p * 256;
            int r = e >> 4, q = (e & 15) * 4;
            float4 v = *(const float4*)&x[(size_t)(t0 + r) * HH + k0 + q];
            float f[4] = {v.x, v.y, v.z, v.w};
            unsigned short h[4], l[4];
            #pragma unroll
            for (int i = 0; i < 4; i++) {
                __nv_bfloat16 hb = __float2bfloat16(f[i]);
                __nv_bfloat16 lb = __float2bfloat16(f[i] - __bfloat162float(hb));
                h[i] = __bfloat16_as_ushort(hb);
                l[i] = __bfloat16_as_ushort(lb);
            }
            *(uint2*)&Ah[r][q] = make_uint2((uint32_t)h[0] | ((uint32_t)h[1] << 16),
                                            (uint32_t)h[2] | ((uint32_t)h[3] << 16));
            *(uint2*)&Al[r][q] = make_uint2((uint32_t)l[0] | ((uint32_t)l[1] << 16),
                                            (uint32_t)l[2] | ((uint32_t)l[3] << 16));
        }
        #pragma unroll
        for (int p = 0; p < 4; p++) {
            int e = tid + p * 256;
            int r = e >> 4, q = (e & 15) * 4;
            size_t go = (size_t)(k0 + r) * 128 + cc * 64 + q;
            *(uint2*)&Bh[r][q] = *(const uint2*)&g_whi[go];
            *(uint2*)&Bl[r][q] = *(const uint2*)&g_wlo[go];
        }
        __syncthreads();

        #pragma unroll
        for (int ks = 0; ks < 4; ks++) {
            wmma::fragment<wmma::matrix_a, 16, 16, 16, __nv_bfloat16, wmma::row_major> ah, al;
            wmma::fragment<wmma::matrix_b, 16, 16, 16, __nv_bfloat16, wmma::row_major> bh, bl;
            wmma::load_matrix_sync(ah, &Ah[m0][ks * 16], 80);
            wmma::load_matrix_sync(al, &Al[m0][ks * 16], 80);
            wmma::load_matrix_sync(bh, &Bh[ks * 16][n0], 80);
            wmma::load_matrix_sync(bl, &Bl[ks * 16][n0], 80);
            wmma::mma_sync(acc, ah, bh, acc);
            wmma::mma_sync(acc, ah, bl, acc);
            wmma::mma_sync(acc, al, bh, acc);
        }
    }

    __syncthreads();
    wmma::store_matrix_sync(&Cs[m0][n0], acc, 80, wmma::mem_row_major);
    __syncthreads();

    float* dst = g_part4 + ((size_t)kq * NTOK + t0) * 128 + cc * 64;
    #pragma unroll
    for (int p = 0; p < 8; p++) {
        int e = tid + p * 256;
        int r = e >> 6, col = e & 63;
        dst[(size_t)r * 128 + col] = Cs[r][col];
    }
}

// ---------------------------------------------------------------------------
// Kernel 3: merge split-K partials + bias -> g_q/g_k, then A/E tables.
// Now 256 blocks x 8 tokens for full-chip parallelism.
// A[s,o] = q[s]@Wb[0:64] + bb
// E[e,o] = k[e]@(Wb[64:128]+Wb[192:256]) + q[e]@Wb[128:192]
// ---------------------------------------------------------------------------
__global__ __launch_bounds__(256) void reduce_ae_kernel(
    const float* __restrict__ bq, const float* __restrict__ bk,
    const float* __restrict__ bb, const float* __restrict__ Wb)
{
    __shared__ float Wbs[256 * NOUT];
    __shared__ float sQK[8][132];
    __shared__ float bbs[NOUT];
    __shared__ float bqs[HSZ], bks[HSZ];

    const int tid = threadIdx.x;
    const int t0  = blockIdx.x * 8;

    #pragma unroll
    for (int p = 0; p < 16; p++)
        Wbs[tid + p * 256] = Wb[tid + p * 256];
    if (tid < NOUT) bbs[tid] = bb[tid];
    if (tid < HSZ)  { bqs[tid] = bq[tid]; bks[tid] = bk[tid]; }
    __syncthreads();

    const float4* gp4 = (const float4*)g_part4;
    {
        int tok = tid >> 5, n4 = tid & 31;       // 256 = 8 tok x 32 n4
        size_t gi = (size_t)(t0 + tok) * 32 + n4;
        float4 v = make_float4(0.f, 0.f, 0.f, 0.f);
        #pragma unroll
        for (int q = 0; q < 4; q++) {
            float4 pv = gp4[(size_t)q * NTOK * 32 + gi];
            v.x += pv.x; v.y += pv.y; v.z += pv.z; v.w += pv.w;
        }
        int n = n4 * 4;
        if (n < 64) { v.x += bqs[n]; v.y += bqs[n+1]; v.z += bqs[n+2]; v.w += bqs[n+3]; }
        else        { v.x += bks[n-64]; v.y += bks[n-63]; v.z += bks[n-62]; v.w += bks[n-61]; }
        *(float4*)&sQK[tok][n] = v;
        int tok_g = t0 + tok;
        if (n4 < 16) ((float4*)(g_q + (size_t)tok_g * HSZ))[n4]      = v;
        else         ((float4*)(g_k + (size_t)tok_g * HSZ))[n4 - 16] = v;
    }
    __syncthreads();

    // 256 threads = 128 A items + 128 E items (8 tok x 16 o each)
    if (tid < 128) {
        int tokL = tid >> 4, o = tid & 15;
        float a = bbs[o];
        #pragma unroll 8
        for (int h = 0; h < 64; h++)
            a += sQK[tokL][h] * Wbs[h * NOUT + o];
        g_A[(t0 + tokL) * NOUT + o] = a;
    } else {
        int e2 = tid - 128;
        int tokL = e2 >> 4, o = e2 & 15;
        float a = 0.f;
        #pragma unroll 8
        for (int h = 0; h < 64; h++) {
            a += sQK[tokL][64 + h] * (Wbs[(64 + h) * NOUT + o] + Wbs[(192 + h) * NOUT + o]);
            a += sQK[tokL][h]      *  Wbs[(128 + h) * NOUT + o];
        }
        g_E[(t0 + tokL) * NOUT + o] = a;
    }
}

// ---------------------------------------------------------------------------
// Kernel 4: FUSED score + scatter, 32x32 pair-tiles; staging pad 33
// (conflict-free STS: bank = (h*33+r) mod 32, consecutive h -> distinct).
// ---------------------------------------------------------------------------
__global__ __launch_bounds__(256) void score_scatter_kernel(float* __restrict__ out)
{
    const int bx = blockIdx.x;   // e tile (32)
    const int by = blockIdx.y;   // s tile (32)
    if (by > bx) return;
    const int b  = blockIdx.z;

    __shared__ float  qs[64][33];   // [h][r] pad 33 -> conflict-free staging
    __shared__ float  ks[64][33];
    __shared__ float  Ss[32][33];
    __shared__ float4 Es[128];
    __shared__ float4 As[128];

    const int tid = threadIdx.x;
    const float* qb = g_q + (size_t)(b * LL + by * 32) * HSZ;
    const float* kb = g_k + (size_t)(b * LL + bx * 32) * HSZ;

    #pragma unroll
    for (int p = 0; p < 8; p++) {
        int e = tid + p * 256;     // 0..2047 = 32 r x 64 h
        int r = e >> 6, h = e & 63;
        qs[h][r] = qb[r * HSZ + h];
        ks[h][r] = kb[r * HSZ + h];
    }
    if (tid < 128)      Es[tid]       = ((const float4*)g_E)[(b * LL + bx * 32) * 4 + tid];
    else if (tid < 256) As[tid - 128] = ((const float4*)g_A)[(b * LL + by * 32) * 4 + (tid - 128)];
    __syncthreads();

    // compute: 32x32 / 256 threads = 2(m) x 2(n) per thread
    const int m0 = (tid >> 4) * 2;
    const int n0 = (tid & 15) * 2;
    float a00 = 0.f, a01 = 0.f, a10 = 0.f, a11 = 0.f;
    #pragma unroll
    for (int h = 0; h < 64; h++) {
        float q0 = qs[h][m0], q1 = qs[h][m0 + 1];
        float k0 = ks[h][n0], k1 = ks[h][n0 + 1];
        a00 += q0 * k0; a01 += q0 * k1;
        a10 += q1 * k0; a11 += q1 * k1;
    }
    Ss[m0][n0] = a00;     Ss[m0][n0 + 1] = a01;
    Ss[m0 + 1][n0] = a10; Ss[m0 + 1][n0 + 1] = a11;
    __syncthreads();

    // store: 256 threads = 2 s-rows x (32 jj x 4 oq); 16 iterations
    const int lane = tid & 127;
    const int jj   = lane >> 2;
    const int oq   = lane & 3;
    const int slh  = tid >> 7;             // 0/1
    const bool diag = (bx == by);
    const float4 ev = Es[lane];
    float4* out4 = (float4*)out;
    const size_t bbase = (size_t)b * NP;

    #pragma unroll 4
    for (int sl2 = 0; sl2 < 16; sl2++) {
        int sl = sl2 * 2 + slh;
        int s  = by * 32 + sl;
        int p0 = ((s * (1025 - s)) >> 1) + bx * 32 - s;
        float  sv = Ss[sl][jj];
        float4 av = As[(sl << 2) | oq];
        float4 r  = make_float4(sv + av.x + ev.x, sv + av.y + ev.y,
                                sv + av.z + ev.z, sv + av.w + ev.w);
        if (!diag || jj >= sl)
            out4[(bbase + p0) * 4 + lane] = r;
    }
}

extern "C" void kernel_launch(void* const* d_in, const int* in_sizes, int n_in,
                              void* d_out, int out_size)
{
    const float* x  = (const float*)d_in[0];
    const float* Wq = (const float*)d_in[1];
    const float* bq = (const float*)d_in[2];
    const float* Wk = (const float*)d_in[3];
    const float* bk = (const float*)d_in[4];
    const float* Wb = (const float*)d_in[5];
    const float* bb = (const float*)d_in[6];
    float* out = (float*)d_out;

    prep_w_kernel<<<96, 256>>>(Wq, Wk);
    wmma_proj_kernel<<<512, 256>>>(x);
    reduce_ae_kernel<<<256, 256>>>(bq, bk, bb, Wb);
    dim3 g2(LL / 32, LL / 32, BN);
    score_scatter_kernel<<<g2, 256>>>(out);
}